// round 1
// baseline (speedup 1.0000x reference)
#include <cuda_runtime.h>
#include <cstdint>
#include <cstddef>

#define BATCH 32
#define NA    32768
#define NG    64
#define NC    91
#define IOU_T 0.45f
#define XCLIP 4.135166556742356f   /* log(1000/16) */

// ---------------- scratch (static device globals; no allocation) ----------------
__device__ unsigned long long g_best[BATCH * NG];   // packed (iou_bits<<32)|(~anchor)
__device__ signed char        g_matched[BATCH * NA];
__device__ float              g_negbuf[BATCH * NA]; // neg cls_loss (0 at fg positions)
__device__ float              g_bboxp[256];
__device__ float              g_fgclsp[256];
__device__ int                g_fgcount[BATCH];
__device__ float              g_negsum[BATCH];

// ---------------- K0: zero accumulators ----------------
__global__ void zero_kernel() {
    int t = threadIdx.x;
    for (int i = t; i < BATCH * NG; i += 256) g_best[i] = 0xFFFFFFFFull; // iou=0, anchor=0
    g_bboxp[t] = 0.f;
    g_fgclsp[t] = 0.f;
    if (t < BATCH) g_fgcount[t] = 0;
}

// ---------------- K1: matching (per-anchor argmax over gts + per-gt argmax over anchors) ----
__global__ void match_kernel(const float4* __restrict__ anchors,
                             const float4* __restrict__ gtb) {
    const int b = blockIdx.y;
    const int a = blockIdx.x * blockDim.x + threadIdx.x;
    const int t = threadIdx.x;

    __shared__ float4             s_gt[NG];
    __shared__ float              s_ga[NG];
    __shared__ unsigned long long s_best[NG];

    if (t < NG) {
        float4 g = gtb[b * NG + t];
        s_gt[t] = g;
        s_ga[t] = (g.z - g.x) * (g.w - g.y);
        s_best[t] = 0xFFFFFFFFull;
    }
    __syncthreads();

    float4 an = anchors[(size_t)b * NA + a];
    float aarea = (an.z - an.x) * (an.w - an.y);

    float bestv = 0.f;
    int   bestg = 0;
    const unsigned pa = 0xFFFFFFFFu - (unsigned)a;   // prefer smaller anchor on iou tie

#pragma unroll 8
    for (int g = 0; g < NG; g++) {
        float4 gb = s_gt[g];
        float tlx = fmaxf(gb.x, an.x), tly = fmaxf(gb.y, an.y);
        float brx = fminf(gb.z, an.z), bry = fminf(gb.w, an.w);
        float w = fmaxf(brx - tlx, 0.f), h = fmaxf(bry - tly, 0.f);
        float inter = w * h;
        bool  ov = inter > 0.f;
        if (__ballot_sync(0xFFFFFFFFu, ov)) {
            float un  = s_ga[g] + aarea - inter + 1e-16f;
            float iou = __fdividef(inter, un);          // 0 when inter==0
            if (iou > bestv) { bestv = iou; bestg = g; } // strict > => first max
            if (ov) {
                unsigned long long p =
                    ((unsigned long long)__float_as_uint(iou) << 32) | (unsigned long long)pa;
                if (p > s_best[g]) atomicMax(&s_best[g], p);  // racy read is safe (monotone)
            }
        }
    }

    g_matched[(size_t)b * NA + a] = (bestv >= IOU_T) ? (signed char)bestg : (signed char)-1;

    __syncthreads();
    if (t < NG) atomicMax(&g_best[b * NG + t], s_best[t]);
}

// ---------------- K1b: best-anchor-per-gt override (sequential last-gt-wins) ----------------
__global__ void override_kernel() {
    int b = threadIdx.x;
    if (b < BATCH) {
        for (int g = 0; g < NG; g++) {
            unsigned a = 0xFFFFFFFFu - (unsigned)(g_best[b * NG + g] & 0xFFFFFFFFull);
            g_matched[(size_t)b * NA + a] = (signed char)g;
        }
    }
}

// ---------------- K2: fused log-softmax loss + giou + neg buffer ----------------
__global__ void loss_kernel(const float*  __restrict__ logits,
                            const float4* __restrict__ reg,
                            const float4* __restrict__ anchors,
                            const float4* __restrict__ gtb,
                            const int*    __restrict__ glab) {
    const int b    = blockIdx.y;
    const int wid  = threadIdx.x >> 5;
    const int lane = threadIdx.x & 31;

    float fgcls = 0.f, bbox = 0.f;
    int   fgc   = 0;
    const int abase = blockIdx.x * 128 + wid * 16;

    for (int i = 0; i < 16; i++) {
        const int a = abase + i;
        const size_t off = ((size_t)b * NA + a) * NC;

        float x0 = logits[off + lane];
        float x1 = logits[off + 32 + lane];
        float x2 = (lane < NC - 64) ? logits[off + 64 + lane] : -1e30f;

        float m = fmaxf(x0, fmaxf(x1, x2));
#pragma unroll
        for (int s = 16; s; s >>= 1) m = fmaxf(m, __shfl_xor_sync(0xFFFFFFFFu, m, s));

        float e = __expf(x0 - m) + __expf(x1 - m) + __expf(x2 - m);
#pragma unroll
        for (int s = 16; s; s >>= 1) e += __shfl_xor_sync(0xFFFFFFFFu, e, s);

        float lse = m + __logf(e);

        const int mt = g_matched[(size_t)b * NA + a];
        const int target = (mt >= 0) ? glab[b * NG + mt] : (NC - 1);
        const int tl = target & 31;
        float l0 = __shfl_sync(0xFFFFFFFFu, x0, tl);
        float l1 = __shfl_sync(0xFFFFFFFFu, x1, tl);
        float l2 = __shfl_sync(0xFFFFFFFFu, x2, tl);
        float lt = (target < 32) ? l0 : ((target < 64) ? l1 : l2);
        float cls = lse - lt;

        if (lane == 0) {
            if (mt >= 0) {
                fgc++;
                fgcls += cls;
                g_negbuf[(size_t)b * NA + a] = 0.f;

                float4 an = anchors[(size_t)b * NA + a];
                float4 rg = reg[(size_t)b * NA + a];
                float4 gb = gtb[b * NG + mt];

                float w  = an.z - an.x, h = an.w - an.y;
                float cx = an.x + 0.5f * w, cy = an.y + 0.5f * h;
                float dw = fminf(rg.z, XCLIP), dh = fminf(rg.w, XCLIP);
                float pcx = rg.x * w + cx,  pcy = rg.y * h + cy;
                float pw  = __expf(dw) * w, ph  = __expf(dh) * h;
                float px1 = pcx - 0.5f * pw, py1 = pcy - 0.5f * ph;
                float px2 = pcx + 0.5f * pw, py2 = pcy + 0.5f * ph;

                float tlx = fmaxf(px1, gb.x), tly = fmaxf(py1, gb.y);
                float brx = fminf(px2, gb.z), bry = fminf(py2, gb.w);
                float iw = fmaxf(brx - tlx, 0.f), ih = fmaxf(bry - tly, 0.f);
                float inter = iw * ih;
                float ap = (px2 - px1) * (py2 - py1);
                float ag = (gb.z - gb.x) * (gb.w - gb.y);
                float un = ap + ag - inter + 1e-16f;
                float iou = inter / un;
                float cw = fmaxf(px2, gb.z) - fminf(px1, gb.x);
                float ch = fmaxf(py2, gb.w) - fminf(py1, gb.y);
                float ac = cw * ch;
                float giou = iou - (ac - un) / fmaxf(ac, 1e-16f);
                giou = fminf(1.f, fmaxf(-1.f, giou));
                bbox += 1.f - giou;
            } else {
                g_negbuf[(size_t)b * NA + a] = cls;
            }
        }
    }

    __shared__ float s_f[8], s_b[8];
    __shared__ int   s_c[8];
    if (lane == 0) { s_f[wid] = fgcls; s_b[wid] = bbox; s_c[wid] = fgc; }
    __syncthreads();
    if (threadIdx.x == 0) {
        float tf = 0.f, tb = 0.f; int tc = 0;
#pragma unroll
        for (int i = 0; i < 8; i++) { tf += s_f[i]; tb += s_b[i]; tc += s_c[i]; }
        int slot = (blockIdx.y * gridDim.x + blockIdx.x) & 255;
        if (tf != 0.f) atomicAdd(&g_fgclsp[slot], tf);
        if (tb != 0.f) atomicAdd(&g_bboxp[slot], tb);
        if (tc)        atomicAdd(&g_fgcount[b], tc);
    }
}

// ---------------- K3: per-batch top-k sum via MSB-first radix select ----------------
__global__ void topk_kernel() {
    const int b = blockIdx.x;
    const int t = threadIdx.x;
    __shared__ int      hist[256];
    __shared__ unsigned s_pref;
    __shared__ int      s_rem;

    int k = 3 * g_fgcount[b];
    if (k <= 0) { if (t == 0) g_negsum[b] = 0.f; return; }
    if (k > NA) k = NA;

    unsigned prefix = 0;
    int rem = k;
    const float* buf = g_negbuf + (size_t)b * NA;

    for (int shift = 24; shift >= 0; shift -= 8) {
        hist[t] = 0;
        __syncthreads();
        const unsigned hmask = (shift == 24) ? 0u : (0xFFFFFFFFu << (shift + 8));
        for (int i = t; i < NA; i += 256) {
            unsigned bits = __float_as_uint(buf[i]);   // nonneg floats: bits order == value order
            if ((bits & hmask) == prefix)
                atomicAdd(&hist[(bits >> shift) & 255], 1);
        }
        __syncthreads();
        if (t == 0) {
            int r = rem, d = 255;
            for (; d > 0; d--) { if (r <= hist[d]) break; r -= hist[d]; }
            s_pref = prefix | ((unsigned)d << shift);
            s_rem  = r;
        }
        __syncthreads();
        prefix = s_pref;
        rem    = s_rem;
        __syncthreads();
    }

    const float thr = __uint_as_float(prefix);
    float sum = 0.f;
    for (int i = t; i < NA; i += 256) {
        float v = buf[i];
        if (__float_as_uint(v) > prefix) sum += v;
    }
    __shared__ float s_sum[256];
    s_sum[t] = sum;
    __syncthreads();
    for (int s = 128; s; s >>= 1) { if (t < s) s_sum[t] += s_sum[t + s]; __syncthreads(); }
    if (t == 0) g_negsum[b] = s_sum[0] + (float)rem * thr;  // tie-exact selection sum
}

// ---------------- K4: finalize ----------------
__global__ void final_kernel(float* __restrict__ out) {
    const int t = threadIdx.x;
    __shared__ float sb[256], sf[256], sn[256];
    __shared__ int   sc[256];
    sb[t] = g_bboxp[t];
    sf[t] = g_fgclsp[t];
    sn[t] = (t < BATCH) ? g_negsum[t] : 0.f;
    sc[t] = (t < BATCH) ? g_fgcount[t] : 0;
    __syncthreads();
    for (int s = 128; s; s >>= 1) {
        if (t < s) { sb[t] += sb[t+s]; sf[t] += sf[t+s]; sn[t] += sn[t+s]; sc[t] += sc[t+s]; }
        __syncthreads();
    }
    if (t == 0) {
        float N = (float)((sc[0] > 1) ? sc[0] : 1);
        out[0] = 2.f * sb[0] / N;
        out[1] = (sf[0] + sn[0]) / N;
    }
}

// ---------------- launch ----------------
extern "C" void kernel_launch(void* const* d_in, const int* in_sizes, int n_in,
                              void* d_out, int out_size) {
    (void)in_sizes; (void)n_in; (void)out_size;
    const float*  logits  = (const float*)d_in[0];
    const float4* reg     = (const float4*)d_in[1];
    const float4* anchors = (const float4*)d_in[2];
    const float4* gtb     = (const float4*)d_in[3];
    const int*    glab    = (const int*)d_in[4];

    zero_kernel<<<1, 256>>>();
    match_kernel<<<dim3(NA / 256, BATCH), 256>>>(anchors, gtb);
    override_kernel<<<1, 32>>>();
    loss_kernel<<<dim3(NA / 128, BATCH), 256>>>(logits, reg, anchors, gtb, glab);
    topk_kernel<<<BATCH, 256>>>();
    final_kernel<<<1, 256>>>((float*)d_out);
}